// round 8
// baseline (speedup 1.0000x reference)
#include <cuda_runtime.h>
#include <math.h>

#define Bn 8
#define Nn 256
#define Dd 256
#define DHh 64
#define BND (Bn * Nn * DHh)      // 131072
#define BNr (Bn * Nn)            // 2048
#define PR 16                    // rows per block in prep kernels

// scratch: Qn,Kn,Vn,Q,K,V
__device__ float g_np[6 * BND];
// folded-weight per-row vectors
__device__ float g_u[BNr * Dd];    // Wk_n2e @ Qn_i
__device__ float g_v[BNr * Dd];    // Wq_e2n @ Kn_j
__device__ float g_c[BNr];         // bk_n2e . Qn_i
__device__ float g_d[BNr];         // bq_e2n . Kn_j
// transposed weights (h-major)
__device__ float g_Wkt[DHh * Dd];
__device__ float g_Wqt[DHh * Dd];

// Reduce two values across the warp in 6 shuffles.
__device__ __forceinline__ void dual_warp_sum(float& a, float& b_, int lane) {
    float send = (lane & 16) ? a : b_;
    float recv = __shfl_xor_sync(0xffffffffu, send, 16);
    float v = (lane & 16) ? (b_ + recv) : (a + recv);
    #pragma unroll
    for (int o = 8; o; o >>= 1) v += __shfl_xor_sync(0xffffffffu, v, o);
    float other = __shfl_xor_sync(0xffffffffu, v, 16);
    a  = (lane & 16) ? other : v;
    b_ = (lane & 16) ? v : other;
}

// ------------------------------------------------------------------
// 6 projections of x, 16 rows per block (weight reuse)
// grid = 128, block = 256
// ------------------------------------------------------------------
__global__ void proj_x_kernel(
    const float* __restrict__ x, const float* __restrict__ mask,
    const float* __restrict__ W0, const float* __restrict__ b0,
    const float* __restrict__ W1, const float* __restrict__ b1,
    const float* __restrict__ W2, const float* __restrict__ b2,
    const float* __restrict__ W3, const float* __restrict__ b3,
    const float* __restrict__ W4, const float* __restrict__ b4,
    const float* __restrict__ W5, const float* __restrict__ b5)
{
    int r0 = blockIdx.x * PR;
    int t = threadIdx.x;
    __shared__ float xs[PR][Dd];
    __shared__ float msk[PR];

    #pragma unroll
    for (int i = 0; i < PR; ++i)
        xs[i][t] = x[(size_t)(r0 + i) * Dd + t];
    if (t < PR) msk[t] = mask[r0 + t];
    __syncthreads();

    int h = t & 63, g = t >> 6;       // group g handles rows 4g..4g+3
    int base = g * 4;

    const float* Ws[6] = {W0, W1, W2, W3, W4, W5};
    const float* bs[6] = {b0, b1, b2, b3, b4, b5};

    #pragma unroll
    for (int p = 0; p < 6; ++p) {
        const float* W = Ws[p];
        float bias = bs[p][h];
        float a0 = bias, a1 = bias, a2 = bias, a3 = bias;
        #pragma unroll 4
        for (int k = 0; k < Dd; ++k) {
            float w = W[k * DHh + h];
            a0 = fmaf(xs[base + 0][k], w, a0);
            a1 = fmaf(xs[base + 1][k], w, a1);
            a2 = fmaf(xs[base + 2][k], w, a2);
            a3 = fmaf(xs[base + 3][k], w, a3);
        }
        float* dst = g_np + (size_t)p * BND + (size_t)(r0 + base) * DHh + h;
        dst[0 * DHh] = a0 * msk[base + 0];
        dst[1 * DHh] = a1 * msk[base + 1];
        dst[2 * DHh] = a2 * msk[base + 2];
        dst[3 * DHh] = a3 * msk[base + 3];
    }
}

__global__ void transpose_w_kernel(const float* __restrict__ Wk,
                                   const float* __restrict__ Wq)
{
    int h = blockIdx.x;
    int d = threadIdx.x;
    g_Wkt[h * Dd + d] = Wk[d * DHh + h];
    g_Wqt[h * Dd + d] = Wq[d * DHh + h];
}

// u/v for 16 rows per block (measured 23us in R6)
// grid = 128, block = 256 (thread owns d)
__global__ void make_uv_kernel(const float* __restrict__ bk,
                               const float* __restrict__ bq)
{
    int r0 = blockIdx.x * PR;
    int t = threadIdx.x;
    __shared__ float qn[PR][DHh];
    __shared__ float kn[PR][DHh];

    #pragma unroll
    for (int i = 0; i < 4; ++i) {
        int idx = t + i * 256;            // 0..1023
        int row = idx >> 6, h = idx & 63;
        qn[row][h] = g_np[(size_t)(r0 + row) * DHh + h];
        kn[row][h] = g_np[(size_t)BND + (size_t)(r0 + row) * DHh + h];
    }
    __syncthreads();

    // u pass
    {
        float au[PR];
        #pragma unroll
        for (int i = 0; i < PR; ++i) au[i] = 0.f;
        #pragma unroll 4
        for (int h = 0; h < DHh; ++h) {
            float w = g_Wkt[h * Dd + t];
            #pragma unroll
            for (int i = 0; i < PR; ++i) au[i] = fmaf(w, qn[i][h], au[i]);
        }
        #pragma unroll
        for (int i = 0; i < PR; ++i)
            g_u[(size_t)(r0 + i) * Dd + t] = au[i];
    }
    // v pass
    {
        float av[PR];
        #pragma unroll
        for (int i = 0; i < PR; ++i) av[i] = 0.f;
        #pragma unroll 4
        for (int h = 0; h < DHh; ++h) {
            float w = g_Wqt[h * Dd + t];
            #pragma unroll
            for (int i = 0; i < PR; ++i) av[i] = fmaf(w, kn[i][h], av[i]);
        }
        #pragma unroll
        for (int i = 0; i < PR; ++i)
            g_v[(size_t)(r0 + i) * Dd + t] = av[i];
    }
    // bias dots
    if (t < PR) {
        float sc = 0.f;
        #pragma unroll 8
        for (int h = 0; h < DHh; ++h) sc = fmaf(bk[h], qn[t][h], sc);
        g_c[r0 + t] = sc;
    } else if (t >= 32 && t < 32 + PR) {
        int row = t - 32;
        float sd2 = 0.f;
        #pragma unroll 8
        for (int h = 0; h < DHh; ++h) sd2 = fmaf(bq[h], kn[row][h], sd2);
        g_d[r0 + row] = sd2;
    }
}

// ------------------------------------------------------------------
// Fused mega-kernel (VERBATIM R5, measured 200us): per (b,i) block
//   phase 1: stream e row-slab -> e_new, online-softmax weighted e-sum
//   phase 2: n2n self attention row (smem K tile)
//   phase 3: x_cross & final mix
// ------------------------------------------------------------------
__global__ void __launch_bounds__(256, 4) fused_kernel(
    const float* __restrict__ e, const float* __restrict__ mask,
    const float* __restrict__ Wv, const float* __restrict__ bv,
    const float* __restrict__ Wmix, const float* __restrict__ bmix,
    float* __restrict__ out_e, float* __restrict__ out_x)
{
    int r = blockIdx.x;
    int b = r >> 8;
    int t = threadIdx.x;
    int wid = t >> 5, lane = t & 31;

    // big buffer: phase1 = s_sm[8][256] (2048 floats), phase2 = K_s[128][65]
    __shared__ float big[128 * 65];
    __shared__ float maskb_s[Nn];
    __shared__ float djs_s[Nn];
    __shared__ float mw[8], lw[8], tw[8];
    __shared__ float gsrow[Dd];
    __shared__ float gt_s;
    __shared__ float Q_s[DHh];
    __shared__ float att[Nn];
    __shared__ float red[256];
    __shared__ float part[4][DHh];
    __shared__ float xsf_s[DHh], xc_s[DHh];

    const float* Vn = g_np + 2 * (size_t)BND;

    maskb_s[t] = mask[b * Nn + t];
    djs_s[t]   = g_d[b * Nn + t];
    __syncthreads();

    int d0 = 4 * lane;
    int d1 = 128 + 4 * lane;

    const float4 u0  = *reinterpret_cast<const float4*>(g_u + (size_t)r * Dd + d0);
    const float4 u1  = *reinterpret_cast<const float4*>(g_u + (size_t)r * Dd + d1);
    const float4 vi0 = *reinterpret_cast<const float4*>(g_v + (size_t)r * Dd + d0);
    const float4 vi1 = *reinterpret_cast<const float4*>(g_v + (size_t)r * Dd + d1);
    const float c_i  = g_c[r];
    const float di   = g_d[r];
    const float xm_i = mask[r];
    const float2 vni = *reinterpret_cast<const float2*>(Vn + (size_t)r * DHh + 2 * lane);

    float m = -INFINITY, l = 0.f, tacc = 0.f;
    float4 s0 = make_float4(0.f, 0.f, 0.f, 0.f);
    float4 s1 = make_float4(0.f, 0.f, 0.f, 0.f);

    const float* erow = e + (size_t)r * Nn * Dd;

    // ---- phase 1: edge streaming loop ----
    int j = wid;
    float4 e0 = __ldcs(reinterpret_cast<const float4*>(erow + (size_t)j * Dd + d0));
    float4 e1 = __ldcs(reinterpret_cast<const float4*>(erow + (size_t)j * Dd + d1));

    for (; j < Nn; ) {
        int jn = j + 8;
        float4 ne0, ne1;
        if (jn < Nn) {
            ne0 = __ldcs(reinterpret_cast<const float4*>(erow + (size_t)jn * Dd + d0));
            ne1 = __ldcs(reinterpret_cast<const float4*>(erow + (size_t)jn * Dd + d1));
        }
        float4 vj0 = *reinterpret_cast<const float4*>(g_v + (size_t)(b * Nn + j) * Dd + d0);
        float4 vj1 = *reinterpret_cast<const float4*>(g_v + (size_t)(b * Nn + j) * Dd + d1);
        float2 vnj = *reinterpret_cast<const float2*>(Vn + (size_t)(b * Nn + j) * DHh + 2 * lane);
        float xm_j = maskb_s[j];
        float dj   = djs_s[j];

        // vdiff = v_j - v_i
        float4 w0, w1;
        w0.x = vj0.x - vi0.x; w0.y = vj0.y - vi0.y;
        w0.z = vj0.z - vi0.z; w0.w = vj0.w - vi0.w;
        w1.x = vj1.x - vi1.x; w1.y = vj1.y - vi1.y;
        w1.z = vj1.z - vi1.z; w1.w = vj1.w - vi1.w;

        float dot0, dotd;
        dot0 = e0.x * u0.x;              dot0 = fmaf(e0.y, u0.y, dot0);
        dot0 = fmaf(e0.z, u0.z, dot0);   dot0 = fmaf(e0.w, u0.w, dot0);
        dot0 = fmaf(e1.x, u1.x, dot0);   dot0 = fmaf(e1.y, u1.y, dot0);
        dot0 = fmaf(e1.z, u1.z, dot0);   dot0 = fmaf(e1.w, u1.w, dot0);
        dotd = e0.x * w0.x;              dotd = fmaf(e0.y, w0.y, dotd);
        dotd = fmaf(e0.z, w0.z, dotd);   dotd = fmaf(e0.w, w0.w, dotd);
        dotd = fmaf(e1.x, w1.x, dotd);   dotd = fmaf(e1.y, w1.y, dotd);
        dotd = fmaf(e1.z, w1.z, dotd);   dotd = fmaf(e1.w, w1.w, dotd);

        dual_warp_sum(dot0, dotd, lane);

        float em = xm_i * xm_j;
        bool am = em > 0.f;

        // n2e online softmax + weighted-e accumulation
        float sc = am ? (dot0 + c_i) * em * 0.125f : -1e9f;
        float mn = fmaxf(m, sc);
        float alpha = __expf(m - mn);
        float pv = __expf(sc - mn);
        l = l * alpha + pv;
        float pve = pv * em;
        tacc = tacc * alpha + pve;
        s0.x = fmaf(s0.x, alpha, pve * e0.x);
        s0.y = fmaf(s0.y, alpha, pve * e0.y);
        s0.z = fmaf(s0.z, alpha, pve * e0.z);
        s0.w = fmaf(s0.w, alpha, pve * e0.w);
        s1.x = fmaf(s1.x, alpha, pve * e1.x);
        s1.y = fmaf(s1.y, alpha, pve * e1.y);
        s1.z = fmaf(s1.z, alpha, pve * e1.z);
        s1.w = fmaf(s1.w, alpha, pve * e1.w);
        m = mn;

        // e2n gating -> e_new: ai = sigmoid((dotd + dj - di)*em/8)
        float o0 = 0.f, o1 = 0.f;
        if (am) {
            float arg = (dotd + dj - di) * em * 0.125f;
            float ai = 1.f / (1.f + __expf(-arg));
            float aj = 1.f - ai;
            o0 = (ai * vnj.x + aj * vni.x) * em;
            o1 = (ai * vnj.y + aj * vni.y) * em;
        }
        __stcg(reinterpret_cast<float2*>(out_e + ((size_t)r * Nn + j) * DHh + 2 * lane),
               make_float2(o0, o1));

        j = jn;
        e0 = ne0; e1 = ne1;
    }

    // merge the 8 warps' online-softmax partials (s_sm = big[w*Dd + d])
    big[wid * Dd + d0 + 0] = s0.x; big[wid * Dd + d0 + 1] = s0.y;
    big[wid * Dd + d0 + 2] = s0.z; big[wid * Dd + d0 + 3] = s0.w;
    big[wid * Dd + d1 + 0] = s1.x; big[wid * Dd + d1 + 1] = s1.y;
    big[wid * Dd + d1 + 2] = s1.z; big[wid * Dd + d1 + 3] = s1.w;
    if (lane == 0) { mw[wid] = m; lw[wid] = l; tw[wid] = tacc; }
    __syncthreads();

    {
        float gm = mw[0];
        #pragma unroll
        for (int w = 1; w < 8; ++w) gm = fmaxf(gm, mw[w]);
        float gl = 0.f, gt = 0.f, gs = 0.f;
        #pragma unroll
        for (int w = 0; w < 8; ++w) {
            float sc2 = __expf(mw[w] - gm);
            gl = fmaf(lw[w], sc2, gl);
            gt = fmaf(tw[w], sc2, gt);
            gs = fmaf(big[w * Dd + t], sc2, gs);
        }
        float invl = 1.f / gl;
        gsrow[t] = gs * invl;
        if (t == 0) gt_s = gt * invl;
    }

    // ---- phase 2: n2n self attention for row r ----
    const float* Q = g_np + 3 * (size_t)BND;
    const float* K = g_np + 4 * (size_t)BND;
    const float* V = g_np + 5 * (size_t)BND;

    if (t < DHh) Q_s[t] = Q[(size_t)r * DHh + t];

    // QK^T row: 2 tiles of 128 K-rows; all 256 threads active (half-dim split)
    for (int tt = 0; tt < 2; ++tt) {
        __syncthreads();  // big free / red free
        for (int idx = t; idx < 128 * 64; idx += 256) {
            int row = idx >> 6, col = idx & 63;
            big[row * 65 + col] = K[(size_t)(b * Nn + tt * 128 + row) * DHh + col];
        }
        __syncthreads();
        int row = t & 127, half = t >> 7;
        float p = 0.f;
        #pragma unroll 8
        for (int d = 0; d < 32; ++d)
            p = fmaf(Q_s[half * 32 + d], big[row * 65 + half * 32 + d], p);
        red[t] = p;
        __syncthreads();
        if (t < 128) att[tt * 128 + t] = red[t] + red[t + 128];
    }
    __syncthreads();

    // masked softmax over the 256 logits (thread t owns j=t)
    {
        float xm_j = maskb_s[t];
        bool am = (xm_i * xm_j) > 0.f;
        float lg = am ? att[t] * 0.125f : -1e9f;
        float wmax = lg;
        #pragma unroll
        for (int o = 16; o; o >>= 1)
            wmax = fmaxf(wmax, __shfl_xor_sync(0xffffffffu, wmax, o));
        if (lane == 0) red[wid] = wmax;
        __syncthreads();
        float gmax = red[0];
        #pragma unroll
        for (int w = 1; w < 8; ++w) gmax = fmaxf(gmax, red[w]);
        float ex = __expf(lg - gmax);
        float wsum = ex;
        #pragma unroll
        for (int o = 16; o; o >>= 1)
            wsum += __shfl_xor_sync(0xffffffffu, wsum, o);
        if (lane == 0) red[8 + wid] = wsum;
        __syncthreads();
        float gsum = 0.f;
        #pragma unroll
        for (int w = 0; w < 8; ++w) gsum += red[8 + w];
        att[t] = ex / gsum;
    }
    __syncthreads();

    // PV: quarter q handles j in [64q, 64q+64)
    {
        int q = t >> 6, h = t & 63;
        float acc = 0.f;
        const float* Vb = V + (size_t)(b * Nn + q * 64) * DHh + h;
        #pragma unroll 8
        for (int jj = 0; jj < 64; ++jj)
            acc = fmaf(att[q * 64 + jj], Vb[(size_t)jj * DHh], acc);
        part[q][h] = acc;
    }
    __syncthreads();
    if (t < DHh)
        xsf_s[t] = (part[0][t] + part[1][t] + part[2][t] + part[3][t]) * xm_i;
    __syncthreads();

    // ---- phase 3: x_cross = gsrow@Wv + gt*bv ; out = [xc,xs]@Wmix + bmix ----
    {
        int q = t >> 6, h = t & 63;
        float acc = (q == 0) ? gt_s * bv[h] : 0.f;
        #pragma unroll 8
        for (int d = 0; d < 64; ++d)
            acc = fmaf(gsrow[q * 64 + d], Wv[(q * 64 + d) * DHh + h], acc);
        part[q][h] = acc;
    }
    __syncthreads();
    if (t < DHh) xc_s[t] = part[0][t] + part[1][t] + part[2][t] + part[3][t];
    __syncthreads();

    if (t < 128) {
        int half = t >> 6, hh = t & 63;
        float o = (half == 0) ? bmix[hh] : 0.f;
        #pragma unroll 8
        for (int k = 0; k < 64; ++k) {
            float src = (half == 0) ? xc_s[k] : xsf_s[k];
            o = fmaf(src, Wmix[(half * 64 + k) * DHh + hh], o);
        }
        part[half][hh] = o;
    }
    __syncthreads();
    if (t < DHh) out_x[(size_t)r * DHh + t] = part[0][t] + part[1][t];
}

extern "C" void kernel_launch(void* const* d_in, const int* in_sizes, int n_in,
                              void* d_out, int out_size)
{
    const float* x       = (const float*)d_in[0];
    const float* e       = (const float*)d_in[1];
    const float* mask    = (const float*)d_in[2];
    const float* W_n2e_q = (const float*)d_in[3];  const float* b_n2e_q = (const float*)d_in[4];
    const float* W_n2e_k = (const float*)d_in[5];  const float* b_n2e_k = (const float*)d_in[6];
    const float* W_n2e_v = (const float*)d_in[7];  const float* b_n2e_v = (const float*)d_in[8];
    const float* W_e2n_q = (const float*)d_in[9];  const float* b_e2n_q = (const float*)d_in[10];
    const float* W_e2n_k = (const float*)d_in[11]; const float* b_e2n_k = (const float*)d_in[12];
    const float* W_e2n_v = (const float*)d_in[13]; const float* b_e2n_v = (const float*)d_in[14];
    const float* W_n2n_q = (const float*)d_in[15]; const float* b_n2n_q = (const float*)d_in[16];
    const float* W_n2n_k = (const float*)d_in[17]; const float* b_n2n_k = (const float*)d_in[18];
    const float* W_n2n_v = (const float*)d_in[19]; const float* b_n2n_v = (const float*)d_in[20];
    const float* W_mix   = (const float*)d_in[21]; const float* b_mix   = (const float*)d_in[22];

    float* out   = (float*)d_out;
    float* out_x = out;
    float* out_e = out + (size_t)Bn * Nn * DHh;

    proj_x_kernel<<<BNr / PR, 256>>>(x, mask,
        W_n2e_q, b_n2e_q,
        W_e2n_k, b_e2n_k,
        W_e2n_v, b_e2n_v,
        W_n2n_q, b_n2n_q,
        W_n2n_k, b_n2n_k,
        W_n2n_v, b_n2n_v);

    transpose_w_kernel<<<DHh, Dd>>>(W_n2e_k, W_e2n_q);
    make_uv_kernel<<<BNr / PR, 256>>>(b_n2e_k, b_e2n_q);

    fused_kernel<<<BNr, 256>>>(e, mask,
        W_n2e_v, b_n2e_v, W_mix, b_mix, out_e, out_x);
}

// round 9
// speedup vs baseline: 1.3911x; 1.3911x over previous
#include <cuda_runtime.h>
#include <math.h>

#define Bn 8
#define Nn 256
#define Dd 256
#define DHh 64
#define BND (Bn * Nn * DHh)      // 131072
#define BNr (Bn * Nn)            // 2048

// scratch: Qn,Kn,Vn,Q,K,V
__device__ float g_np[6 * BND];
// folded-weight per-row vectors
__device__ float g_u[BNr * Dd];    // Wk_n2e @ Qn_i
__device__ float g_v[BNr * Dd];    // Wq_e2n @ Kn_j
__device__ float g_c[BNr];         // bk_n2e . Qn_i
__device__ float g_d[BNr];         // bq_e2n . Kn_j
// transposed weights (h-major)
__device__ float g_Wkt[DHh * Dd];
__device__ float g_Wqt[DHh * Dd];

// Reduce two values across the warp in 6 shuffles.
__device__ __forceinline__ void dual_warp_sum(float& a, float& b_, int lane) {
    float send = (lane & 16) ? a : b_;
    float recv = __shfl_xor_sync(0xffffffffu, send, 16);
    float v = (lane & 16) ? (b_ + recv) : (a + recv);
    #pragma unroll
    for (int o = 8; o; o >>= 1) v += __shfl_xor_sync(0xffffffffu, v, o);
    float other = __shfl_xor_sync(0xffffffffu, v, 16);
    a  = (lane & 16) ? other : v;
    b_ = (lane & 16) ? v : other;
}

// ------------------------------------------------------------------
// 6 projections of x. grid = (64 row-tiles, 6 proj), block = 256.
// 32 rows per block; thread owns col h for 8 rows.
// ------------------------------------------------------------------
__global__ void proj_x_kernel(
    const float* __restrict__ x, const float* __restrict__ mask,
    const float* __restrict__ W0, const float* __restrict__ b0,
    const float* __restrict__ W1, const float* __restrict__ b1,
    const float* __restrict__ W2, const float* __restrict__ b2,
    const float* __restrict__ W3, const float* __restrict__ b3,
    const float* __restrict__ W4, const float* __restrict__ b4,
    const float* __restrict__ W5, const float* __restrict__ b5)
{
    int p  = blockIdx.y;
    int r0 = blockIdx.x * 32;
    int t  = threadIdx.x;

    __shared__ float xs[32][Dd];
    __shared__ float msk[32];

    // linear copy: x tile is contiguous 32*256 floats
    {
        const float4* src = reinterpret_cast<const float4*>(x + (size_t)r0 * Dd);
        float4* dst = reinterpret_cast<float4*>(&xs[0][0]);
        #pragma unroll
        for (int i = 0; i < 8; ++i)
            dst[t + i * 256] = src[t + i * 256];
        if (t < 32) msk[t] = mask[r0 + t];
    }
    __syncthreads();

    const float* W;
    const float* bb;
    switch (p) {
        case 0: W = W0; bb = b0; break;
        case 1: W = W1; bb = b1; break;
        case 2: W = W2; bb = b2; break;
        case 3: W = W3; bb = b3; break;
        case 4: W = W4; bb = b4; break;
        default: W = W5; bb = b5; break;
    }

    int h = t & 63, rg = t >> 6;      // rg owns rows rg*8 .. rg*8+7
    int rb = rg * 8;
    float acc[8];
    float bias = bb[h];
    #pragma unroll
    for (int i = 0; i < 8; ++i) acc[i] = bias;

    #pragma unroll 4
    for (int k = 0; k < Dd; ++k) {
        float w = W[k * DHh + h];
        #pragma unroll
        for (int i = 0; i < 8; ++i)
            acc[i] = fmaf(xs[rb + i][k], w, acc[i]);
    }

    float* dst = g_np + (size_t)p * BND + (size_t)(r0 + rb) * DHh + h;
    #pragma unroll
    for (int i = 0; i < 8; ++i)
        dst[(size_t)i * DHh] = acc[i] * msk[rb + i];
}

__global__ void transpose_w_kernel(const float* __restrict__ Wk,
                                   const float* __restrict__ Wq)
{
    int h = blockIdx.x;
    int d = threadIdx.x;
    g_Wkt[h * Dd + d] = Wk[d * DHh + h];
    g_Wqt[h * Dd + d] = Wq[d * DHh + h];
}

// ------------------------------------------------------------------
// u/v GEMM: grid = (64 row-tiles, 4 col-tiles), block = 256.
// 32 rows x 64 d-cols per block, u and v together.
// ------------------------------------------------------------------
__global__ void make_uv_kernel()
{
    int r0 = blockIdx.x * 32;
    int d0 = blockIdx.y * 64;
    int t  = threadIdx.x;

    __shared__ float qn[32][DHh];
    __shared__ float kn[32][DHh];

    {
        // linear copies: 32*64 floats each, contiguous
        const float4* srcq = reinterpret_cast<const float4*>(g_np + (size_t)r0 * DHh);
        const float4* srck = reinterpret_cast<const float4*>(g_np + (size_t)BND + (size_t)r0 * DHh);
        float4* dq = reinterpret_cast<float4*>(&qn[0][0]);
        float4* dk = reinterpret_cast<float4*>(&kn[0][0]);
        dq[t] = srcq[t];
        dk[t] = srck[t];
        if (t < 256 - 0) { /* 512 float4 total, 256 threads, second batch: */ }
        dq[t + 256] = srcq[t + 256];
        dk[t + 256] = srck[t + 256];
    }
    __syncthreads();

    int dd = t & 63, rg = t >> 6;     // rg owns rows rg*8 .. rg*8+7
    int rb = rg * 8;
    int d  = d0 + dd;

    float au[8], av[8];
    #pragma unroll
    for (int i = 0; i < 8; ++i) { au[i] = 0.f; av[i] = 0.f; }

    #pragma unroll 2
    for (int h = 0; h < DHh; ++h) {
        float wu = g_Wkt[h * Dd + d];
        float wv = g_Wqt[h * Dd + d];
        #pragma unroll
        for (int i = 0; i < 8; ++i) {
            au[i] = fmaf(wu, qn[rb + i][h], au[i]);
            av[i] = fmaf(wv, kn[rb + i][h], av[i]);
        }
    }

    #pragma unroll
    for (int i = 0; i < 8; ++i) {
        g_u[(size_t)(r0 + rb + i) * Dd + d] = au[i];
        g_v[(size_t)(r0 + rb + i) * Dd + d] = av[i];
    }
}

// c_r = bk . Qn_r ; d_r = bq . Kn_r   (grid 8, block 256)
__global__ void bias_cd_kernel(const float* __restrict__ bk,
                               const float* __restrict__ bq)
{
    int r = blockIdx.x * 256 + threadIdx.x;
    const float* qn = g_np + (size_t)r * DHh;
    const float* kn = g_np + (size_t)BND + (size_t)r * DHh;
    float sc = 0.f, sd = 0.f;
    #pragma unroll 8
    for (int h = 0; h < DHh; ++h) {
        sc = fmaf(bk[h], qn[h], sc);
        sd = fmaf(bq[h], kn[h], sd);
    }
    g_c[r] = sc;
    g_d[r] = sd;
}

// ------------------------------------------------------------------
// Fused mega-kernel (VERBATIM R5, measured ~198us): per (b,i) block
// ------------------------------------------------------------------
__global__ void __launch_bounds__(256, 4) fused_kernel(
    const float* __restrict__ e, const float* __restrict__ mask,
    const float* __restrict__ Wv, const float* __restrict__ bv,
    const float* __restrict__ Wmix, const float* __restrict__ bmix,
    float* __restrict__ out_e, float* __restrict__ out_x)
{
    int r = blockIdx.x;
    int b = r >> 8;
    int t = threadIdx.x;
    int wid = t >> 5, lane = t & 31;

    __shared__ float big[128 * 65];
    __shared__ float maskb_s[Nn];
    __shared__ float djs_s[Nn];
    __shared__ float mw[8], lw[8], tw[8];
    __shared__ float gsrow[Dd];
    __shared__ float gt_s;
    __shared__ float Q_s[DHh];
    __shared__ float att[Nn];
    __shared__ float red[256];
    __shared__ float part[4][DHh];
    __shared__ float xsf_s[DHh], xc_s[DHh];

    const float* Vn = g_np + 2 * (size_t)BND;

    maskb_s[t] = mask[b * Nn + t];
    djs_s[t]   = g_d[b * Nn + t];
    __syncthreads();

    int d0 = 4 * lane;
    int d1 = 128 + 4 * lane;

    const float4 u0  = *reinterpret_cast<const float4*>(g_u + (size_t)r * Dd + d0);
    const float4 u1  = *reinterpret_cast<const float4*>(g_u + (size_t)r * Dd + d1);
    const float4 vi0 = *reinterpret_cast<const float4*>(g_v + (size_t)r * Dd + d0);
    const float4 vi1 = *reinterpret_cast<const float4*>(g_v + (size_t)r * Dd + d1);
    const float c_i  = g_c[r];
    const float di   = g_d[r];
    const float xm_i = mask[r];
    const float2 vni = *reinterpret_cast<const float2*>(Vn + (size_t)r * DHh + 2 * lane);

    float m = -INFINITY, l = 0.f, tacc = 0.f;
    float4 s0 = make_float4(0.f, 0.f, 0.f, 0.f);
    float4 s1 = make_float4(0.f, 0.f, 0.f, 0.f);

    const float* erow = e + (size_t)r * Nn * Dd;

    // ---- phase 1: edge streaming loop ----
    int j = wid;
    float4 e0 = __ldcs(reinterpret_cast<const float4*>(erow + (size_t)j * Dd + d0));
    float4 e1 = __ldcs(reinterpret_cast<const float4*>(erow + (size_t)j * Dd + d1));

    for (; j < Nn; ) {
        int jn = j + 8;
        float4 ne0, ne1;
        if (jn < Nn) {
            ne0 = __ldcs(reinterpret_cast<const float4*>(erow + (size_t)jn * Dd + d0));
            ne1 = __ldcs(reinterpret_cast<const float4*>(erow + (size_t)jn * Dd + d1));
        }
        float4 vj0 = *reinterpret_cast<const float4*>(g_v + (size_t)(b * Nn + j) * Dd + d0);
        float4 vj1 = *reinterpret_cast<const float4*>(g_v + (size_t)(b * Nn + j) * Dd + d1);
        float2 vnj = *reinterpret_cast<const float2*>(Vn + (size_t)(b * Nn + j) * DHh + 2 * lane);
        float xm_j = maskb_s[j];
        float dj   = djs_s[j];

        float4 w0, w1;
        w0.x = vj0.x - vi0.x; w0.y = vj0.y - vi0.y;
        w0.z = vj0.z - vi0.z; w0.w = vj0.w - vi0.w;
        w1.x = vj1.x - vi1.x; w1.y = vj1.y - vi1.y;
        w1.z = vj1.z - vi1.z; w1.w = vj1.w - vi1.w;

        float dot0, dotd;
        dot0 = e0.x * u0.x;              dot0 = fmaf(e0.y, u0.y, dot0);
        dot0 = fmaf(e0.z, u0.z, dot0);   dot0 = fmaf(e0.w, u0.w, dot0);
        dot0 = fmaf(e1.x, u1.x, dot0);   dot0 = fmaf(e1.y, u1.y, dot0);
        dot0 = fmaf(e1.z, u1.z, dot0);   dot0 = fmaf(e1.w, u1.w, dot0);
        dotd = e0.x * w0.x;              dotd = fmaf(e0.y, w0.y, dotd);
        dotd = fmaf(e0.z, w0.z, dotd);   dotd = fmaf(e0.w, w0.w, dotd);
        dotd = fmaf(e1.x, w1.x, dotd);   dotd = fmaf(e1.y, w1.y, dotd);
        dotd = fmaf(e1.z, w1.z, dotd);   dotd = fmaf(e1.w, w1.w, dotd);

        dual_warp_sum(dot0, dotd, lane);

        float em = xm_i * xm_j;
        bool am = em > 0.f;

        float sc = am ? (dot0 + c_i) * em * 0.125f : -1e9f;
        float mn = fmaxf(m, sc);
        float alpha = __expf(m - mn);
        float pv = __expf(sc - mn);
        l = l * alpha + pv;
        float pve = pv * em;
        tacc = tacc * alpha + pve;
        s0.x = fmaf(s0.x, alpha, pve * e0.x);
        s0.y = fmaf(s0.y, alpha, pve * e0.y);
        s0.z = fmaf(s0.z, alpha, pve * e0.z);
        s0.w = fmaf(s0.w, alpha, pve * e0.w);
        s1.x = fmaf(s1.x, alpha, pve * e1.x);
        s1.y = fmaf(s1.y, alpha, pve * e1.y);
        s1.z = fmaf(s1.z, alpha, pve * e1.z);
        s1.w = fmaf(s1.w, alpha, pve * e1.w);
        m = mn;

        float o0 = 0.f, o1 = 0.f;
        if (am) {
            float arg = (dotd + dj - di) * em * 0.125f;
            float ai = 1.f / (1.f + __expf(-arg));
            float aj = 1.f - ai;
            o0 = (ai * vnj.x + aj * vni.x) * em;
            o1 = (ai * vnj.y + aj * vni.y) * em;
        }
        __stcg(reinterpret_cast<float2*>(out_e + ((size_t)r * Nn + j) * DHh + 2 * lane),
               make_float2(o0, o1));

        j = jn;
        e0 = ne0; e1 = ne1;
    }

    big[wid * Dd + d0 + 0] = s0.x; big[wid * Dd + d0 + 1] = s0.y;
    big[wid * Dd + d0 + 2] = s0.z; big[wid * Dd + d0 + 3] = s0.w;
    big[wid * Dd + d1 + 0] = s1.x; big[wid * Dd + d1 + 1] = s1.y;
    big[wid * Dd + d1 + 2] = s1.z; big[wid * Dd + d1 + 3] = s1.w;
    if (lane == 0) { mw[wid] = m; lw[wid] = l; tw[wid] = tacc; }
    __syncthreads();

    {
        float gm = mw[0];
        #pragma unroll
        for (int w = 1; w < 8; ++w) gm = fmaxf(gm, mw[w]);
        float gl = 0.f, gt = 0.f, gs = 0.f;
        #pragma unroll
        for (int w = 0; w < 8; ++w) {
            float sc2 = __expf(mw[w] - gm);
            gl = fmaf(lw[w], sc2, gl);
            gt = fmaf(tw[w], sc2, gt);
            gs = fmaf(big[w * Dd + t], sc2, gs);
        }
        float invl = 1.f / gl;
        gsrow[t] = gs * invl;
        if (t == 0) gt_s = gt * invl;
    }

    // ---- phase 2: n2n self attention for row r ----
    const float* Q = g_np + 3 * (size_t)BND;
    const float* K = g_np + 4 * (size_t)BND;
    const float* V = g_np + 5 * (size_t)BND;

    if (t < DHh) Q_s[t] = Q[(size_t)r * DHh + t];

    for (int tt = 0; tt < 2; ++tt) {
        __syncthreads();
        for (int idx = t; idx < 128 * 64; idx += 256) {
            int row = idx >> 6, col = idx & 63;
            big[row * 65 + col] = K[(size_t)(b * Nn + tt * 128 + row) * DHh + col];
        }
        __syncthreads();
        int row = t & 127, half = t >> 7;
        float p = 0.f;
        #pragma unroll 8
        for (int d = 0; d < 32; ++d)
            p = fmaf(Q_s[half * 32 + d], big[row * 65 + half * 32 + d], p);
        red[t] = p;
        __syncthreads();
        if (t < 128) att[tt * 128 + t] = red[t] + red[t + 128];
    }
    __syncthreads();

    {
        float xm_j = maskb_s[t];
        bool am = (xm_i * xm_j) > 0.f;
        float lg = am ? att[t] * 0.125f : -1e9f;
        float wmax = lg;
        #pragma unroll
        for (int o = 16; o; o >>= 1)
            wmax = fmaxf(wmax, __shfl_xor_sync(0xffffffffu, wmax, o));
        if (lane == 0) red[wid] = wmax;
        __syncthreads();
        float gmax = red[0];
        #pragma unroll
        for (int w = 1; w < 8; ++w) gmax = fmaxf(gmax, red[w]);
        float ex = __expf(lg - gmax);
        float wsum = ex;
        #pragma unroll
        for (int o = 16; o; o >>= 1)
            wsum += __shfl_xor_sync(0xffffffffu, wsum, o);
        if (lane == 0) red[8 + wid] = wsum;
        __syncthreads();
        float gsum = 0.f;
        #pragma unroll
        for (int w = 0; w < 8; ++w) gsum += red[8 + w];
        att[t] = ex / gsum;
    }
    __syncthreads();

    {
        int q = t >> 6, h = t & 63;
        float acc = 0.f;
        const float* Vb = V + (size_t)(b * Nn + q * 64) * DHh + h;
        #pragma unroll 8
        for (int jj = 0; jj < 64; ++jj)
            acc = fmaf(att[q * 64 + jj], Vb[(size_t)jj * DHh], acc);
        part[q][h] = acc;
    }
    __syncthreads();
    if (t < DHh)
        xsf_s[t] = (part[0][t] + part[1][t] + part[2][t] + part[3][t]) * xm_i;
    __syncthreads();

    {
        int q = t >> 6, h = t & 63;
        float acc = (q == 0) ? gt_s * bv[h] : 0.f;
        #pragma unroll 8
        for (int d = 0; d < 64; ++d)
            acc = fmaf(gsrow[q * 64 + d], Wv[(q * 64 + d) * DHh + h], acc);
        part[q][h] = acc;
    }
    __syncthreads();
    if (t < DHh) xc_s[t] = part[0][t] + part[1][t] + part[2][t] + part[3][t];
    __syncthreads();

    if (t < 128) {
        int half = t >> 6, hh = t & 63;
        float o = (half == 0) ? bmix[hh] : 0.f;
        #pragma unroll 8
        for (int k = 0; k < 64; ++k) {
            float src = (half == 0) ? xc_s[k] : xsf_s[k];
            o = fmaf(src, Wmix[(half * 64 + k) * DHh + hh], o);
        }
        part[half][hh] = o;
    }
    __syncthreads();
    if (t < DHh) out_x[(size_t)r * DHh + t] = part[0][t] + part[1][t];
}

extern "C" void kernel_launch(void* const* d_in, const int* in_sizes, int n_in,
                              void* d_out, int out_size)
{
    const float* x       = (const float*)d_in[0];
    const float* e       = (const float*)d_in[1];
    const float* mask    = (const float*)d_in[2];
    const float* W_n2e_q = (const float*)d_in[3];  const float* b_n2e_q = (const float*)d_in[4];
    const float* W_n2e_k = (const float*)d_in[5];  const float* b_n2e_k = (const float*)d_in[6];
    const float* W_n2e_v = (const float*)d_in[7];  const float* b_n2e_v = (const float*)d_in[8];
    const float* W_e2n_q = (const float*)d_in[9];  const float* b_e2n_q = (const float*)d_in[10];
    const float* W_e2n_k = (const float*)d_in[11]; const float* b_e2n_k = (const float*)d_in[12];
    const float* W_e2n_v = (const float*)d_in[13]; const float* b_e2n_v = (const float*)d_in[14];
    const float* W_n2n_q = (const float*)d_in[15]; const float* b_n2n_q = (const float*)d_in[16];
    const float* W_n2n_k = (const float*)d_in[17]; const float* b_n2n_k = (const float*)d_in[18];
    const float* W_n2n_v = (const float*)d_in[19]; const float* b_n2n_v = (const float*)d_in[20];
    const float* W_mix   = (const float*)d_in[21]; const float* b_mix   = (const float*)d_in[22];

    float* out   = (float*)d_out;
    float* out_x = out;
    float* out_e = out + (size_t)Bn * Nn * DHh;

    proj_x_kernel<<<dim3(64, 6), 256>>>(x, mask,
        W_n2e_q, b_n2e_q,   // slot0 = Qn
        W_e2n_k, b_e2n_k,   // slot1 = Kn
        W_e2n_v, b_e2n_v,   // slot2 = Vn
        W_n2n_q, b_n2n_q,   // slot3 = Q
        W_n2n_k, b_n2n_k,   // slot4 = K
        W_n2n_v, b_n2n_v);  // slot5 = V

    transpose_w_kernel<<<DHh, Dd>>>(W_n2e_k, W_e2n_q);
    make_uv_kernel<<<dim3(64, 4), 256>>>();
    bias_cd_kernel<<<8, 256>>>(b_n2e_k, b_e2n_q);

    fused_kernel<<<BNr, 256>>>(e, mask,
        W_n2e_v, b_n2e_v, W_mix, b_mix, out_e, out_x);
}

// round 10
// speedup vs baseline: 1.5109x; 1.0861x over previous
#include <cuda_runtime.h>
#include <math.h>

#define Bn 8
#define Nn 256
#define Dd 256
#define DHh 64
#define BND (Bn * Nn * DHh)      // 131072
#define BNr (Bn * Nn)            // 2048

// scratch: Qn,Kn,Vn,Q,K,V
__device__ float g_np[6 * BND];
// folded-weight per-row vectors
__device__ float g_u[BNr * Dd];    // Wk_n2e @ Qn_i
__device__ float g_v[BNr * Dd];    // Wq_e2n @ Kn_j
__device__ float g_c[BNr];         // bk_n2e . Qn_i
__device__ float g_d[BNr];         // bq_e2n . Kn_j
// transposed weights (h-major)
__device__ float g_Wkt[DHh * Dd];
__device__ float g_Wqt[DHh * Dd];

// Reduce two values across the warp in 6 shuffles.
__device__ __forceinline__ void dual_warp_sum(float& a, float& b_, int lane) {
    float send = (lane & 16) ? a : b_;
    float recv = __shfl_xor_sync(0xffffffffu, send, 16);
    float v = (lane & 16) ? (b_ + recv) : (a + recv);
    #pragma unroll
    for (int o = 8; o; o >>= 1) v += __shfl_xor_sync(0xffffffffu, v, o);
    float other = __shfl_xor_sync(0xffffffffu, v, 16);
    a  = (lane & 16) ? other : v;
    b_ = (lane & 16) ? v : other;
}

// ------------------------------------------------------------------
// 6 projections of x + (y==6) weight transpose.
// grid = (64 row-tiles, 7), block = 256. 32 rows/block.
// ------------------------------------------------------------------
__global__ void proj_x_kernel(
    const float* __restrict__ x, const float* __restrict__ mask,
    const float* __restrict__ W0, const float* __restrict__ b0,
    const float* __restrict__ W1, const float* __restrict__ b1,
    const float* __restrict__ W2, const float* __restrict__ b2,
    const float* __restrict__ W3, const float* __restrict__ b3,
    const float* __restrict__ W4, const float* __restrict__ b4,
    const float* __restrict__ W5, const float* __restrict__ b5,
    const float* __restrict__ Wkfold, const float* __restrict__ Wqfold)
{
    int p  = blockIdx.y;
    int t  = threadIdx.x;

    if (p == 6) {
        // transpose fold: block x owns output row h = blockIdx.x
        int h = blockIdx.x;
        g_Wkt[h * Dd + t] = Wkfold[t * DHh + h];
        g_Wqt[h * Dd + t] = Wqfold[t * DHh + h];
        return;
    }

    int r0 = blockIdx.x * 32;
    __shared__ float xs[32][Dd];
    __shared__ float msk[32];

    {
        const float4* src = reinterpret_cast<const float4*>(x + (size_t)r0 * Dd);
        float4* dst = reinterpret_cast<float4*>(&xs[0][0]);
        #pragma unroll
        for (int i = 0; i < 8; ++i)
            dst[t + i * 256] = src[t + i * 256];
        if (t < 32) msk[t] = mask[r0 + t];
    }
    __syncthreads();

    const float* W;
    const float* bb;
    switch (p) {
        case 0: W = W0; bb = b0; break;
        case 1: W = W1; bb = b1; break;
        case 2: W = W2; bb = b2; break;
        case 3: W = W3; bb = b3; break;
        case 4: W = W4; bb = b4; break;
        default: W = W5; bb = b5; break;
    }

    int h = t & 63, rg = t >> 6;      // rg owns rows rg*8 .. rg*8+7
    int rb = rg * 8;
    float acc[8];
    float bias = bb[h];
    #pragma unroll
    for (int i = 0; i < 8; ++i) acc[i] = bias;

    #pragma unroll 2
    for (int k = 0; k < Dd; k += 4) {
        float w0 = W[(k + 0) * DHh + h];
        float w1 = W[(k + 1) * DHh + h];
        float w2 = W[(k + 2) * DHh + h];
        float w3 = W[(k + 3) * DHh + h];
        #pragma unroll
        for (int i = 0; i < 8; ++i) {
            float4 xv = *reinterpret_cast<const float4*>(&xs[rb + i][k]);
            acc[i] = fmaf(xv.x, w0, acc[i]);
            acc[i] = fmaf(xv.y, w1, acc[i]);
            acc[i] = fmaf(xv.z, w2, acc[i]);
            acc[i] = fmaf(xv.w, w3, acc[i]);
        }
    }

    float* dst = g_np + (size_t)p * BND + (size_t)(r0 + rb) * DHh + h;
    #pragma unroll
    for (int i = 0; i < 8; ++i)
        dst[(size_t)i * DHh] = acc[i] * msk[rb + i];
}

// ------------------------------------------------------------------
// u/v GEMM + (y==0) bias dots. grid = (64, 4), block = 256.
// 32 rows x 64 d-cols per block; u-pass then v-pass (reg pressure).
// ------------------------------------------------------------------
__global__ void make_uv_kernel(const float* __restrict__ bk,
                               const float* __restrict__ bq)
{
    int r0 = blockIdx.x * 32;
    int d0 = blockIdx.y * 64;
    int t  = threadIdx.x;

    __shared__ float qn[32][DHh];
    __shared__ float kn[32][DHh];

    {
        const float4* srcq = reinterpret_cast<const float4*>(g_np + (size_t)r0 * DHh);
        const float4* srck = reinterpret_cast<const float4*>(g_np + (size_t)BND + (size_t)r0 * DHh);
        float4* dq = reinterpret_cast<float4*>(&qn[0][0]);
        float4* dk = reinterpret_cast<float4*>(&kn[0][0]);
        dq[t] = srcq[t];
        dk[t] = srck[t];
        dq[t + 256] = srcq[t + 256];
        dk[t + 256] = srck[t + 256];
    }
    __syncthreads();

    int dd = t & 63, rg = t >> 6;
    int rb = rg * 8;
    int d  = d0 + dd;

    // ---- u pass ----
    {
        float au[8];
        #pragma unroll
        for (int i = 0; i < 8; ++i) au[i] = 0.f;
        #pragma unroll 2
        for (int h = 0; h < DHh; h += 4) {
            float w0 = g_Wkt[(h + 0) * Dd + d];
            float w1 = g_Wkt[(h + 1) * Dd + d];
            float w2 = g_Wkt[(h + 2) * Dd + d];
            float w3 = g_Wkt[(h + 3) * Dd + d];
            #pragma unroll
            for (int i = 0; i < 8; ++i) {
                float4 qv = *reinterpret_cast<const float4*>(&qn[rb + i][h]);
                au[i] = fmaf(qv.x, w0, au[i]);
                au[i] = fmaf(qv.y, w1, au[i]);
                au[i] = fmaf(qv.z, w2, au[i]);
                au[i] = fmaf(qv.w, w3, au[i]);
            }
        }
        #pragma unroll
        for (int i = 0; i < 8; ++i)
            g_u[(size_t)(r0 + rb + i) * Dd + d] = au[i];
    }
    // ---- v pass ----
    {
        float av[8];
        #pragma unroll
        for (int i = 0; i < 8; ++i) av[i] = 0.f;
        #pragma unroll 2
        for (int h = 0; h < DHh; h += 4) {
            float w0 = g_Wqt[(h + 0) * Dd + d];
            float w1 = g_Wqt[(h + 1) * Dd + d];
            float w2 = g_Wqt[(h + 2) * Dd + d];
            float w3 = g_Wqt[(h + 3) * Dd + d];
            #pragma unroll
            for (int i = 0; i < 8; ++i) {
                float4 kv = *reinterpret_cast<const float4*>(&kn[rb + i][h]);
                av[i] = fmaf(kv.x, w0, av[i]);
                av[i] = fmaf(kv.y, w1, av[i]);
                av[i] = fmaf(kv.z, w2, av[i]);
                av[i] = fmaf(kv.w, w3, av[i]);
            }
        }
        #pragma unroll
        for (int i = 0; i < 8; ++i)
            g_v[(size_t)(r0 + rb + i) * Dd + d] = av[i];
    }

    // ---- bias dots (only 1 of 4 col-tiles does it) ----
    if (blockIdx.y == 0) {
        if (t < 32) {
            float sc = 0.f;
            #pragma unroll 8
            for (int h = 0; h < DHh; ++h) sc = fmaf(bk[h], qn[t][h], sc);
            g_c[r0 + t] = sc;
        } else if (t < 64) {
            int row = t - 32;
            float sd = 0.f;
            #pragma unroll 8
            for (int h = 0; h < DHh; ++h) sd = fmaf(bq[h], kn[row][h], sd);
            g_d[r0 + row] = sd;
        }
    }
}

// ------------------------------------------------------------------
// Fused mega-kernel (VERBATIM R5/R8, measured ~198us): per (b,i) block
// ------------------------------------------------------------------
__global__ void __launch_bounds__(256, 4) fused_kernel(
    const float* __restrict__ e, const float* __restrict__ mask,
    const float* __restrict__ Wv, const float* __restrict__ bv,
    const float* __restrict__ Wmix, const float* __restrict__ bmix,
    float* __restrict__ out_e, float* __restrict__ out_x)
{
    int r = blockIdx.x;
    int b = r >> 8;
    int t = threadIdx.x;
    int wid = t >> 5, lane = t & 31;

    __shared__ float big[128 * 65];
    __shared__ float maskb_s[Nn];
    __shared__ float djs_s[Nn];
    __shared__ float mw[8], lw[8], tw[8];
    __shared__ float gsrow[Dd];
    __shared__ float gt_s;
    __shared__ float Q_s[DHh];
    __shared__ float att[Nn];
    __shared__ float red[256];
    __shared__ float part[4][DHh];
    __shared__ float xsf_s[DHh], xc_s[DHh];

    const float* Vn = g_np + 2 * (size_t)BND;

    maskb_s[t] = mask[b * Nn + t];
    djs_s[t]   = g_d[b * Nn + t];
    __syncthreads();

    int d0 = 4 * lane;
    int d1 = 128 + 4 * lane;

    const float4 u0  = *reinterpret_cast<const float4*>(g_u + (size_t)r * Dd + d0);
    const float4 u1  = *reinterpret_cast<const float4*>(g_u + (size_t)r * Dd + d1);
    const float4 vi0 = *reinterpret_cast<const float4*>(g_v + (size_t)r * Dd + d0);
    const float4 vi1 = *reinterpret_cast<const float4*>(g_v + (size_t)r * Dd + d1);
    const float c_i  = g_c[r];
    const float di   = g_d[r];
    const float xm_i = mask[r];
    const float2 vni = *reinterpret_cast<const float2*>(Vn + (size_t)r * DHh + 2 * lane);

    float m = -INFINITY, l = 0.f, tacc = 0.f;
    float4 s0 = make_float4(0.f, 0.f, 0.f, 0.f);
    float4 s1 = make_float4(0.f, 0.f, 0.f, 0.f);

    const float* erow = e + (size_t)r * Nn * Dd;

    // ---- phase 1: edge streaming loop ----
    int j = wid;
    float4 e0 = __ldcs(reinterpret_cast<const float4*>(erow + (size_t)j * Dd + d0));
    float4 e1 = __ldcs(reinterpret_cast<const float4*>(erow + (size_t)j * Dd + d1));

    for (; j < Nn; ) {
        int jn = j + 8;
        float4 ne0, ne1;
        if (jn < Nn) {
            ne0 = __ldcs(reinterpret_cast<const float4*>(erow + (size_t)jn * Dd + d0));
            ne1 = __ldcs(reinterpret_cast<const float4*>(erow + (size_t)jn * Dd + d1));
        }
        float4 vj0 = *reinterpret_cast<const float4*>(g_v + (size_t)(b * Nn + j) * Dd + d0);
        float4 vj1 = *reinterpret_cast<const float4*>(g_v + (size_t)(b * Nn + j) * Dd + d1);
        float2 vnj = *reinterpret_cast<const float2*>(Vn + (size_t)(b * Nn + j) * DHh + 2 * lane);
        float xm_j = maskb_s[j];
        float dj   = djs_s[j];

        float4 w0, w1;
        w0.x = vj0.x - vi0.x; w0.y = vj0.y - vi0.y;
        w0.z = vj0.z - vi0.z; w0.w = vj0.w - vi0.w;
        w1.x = vj1.x - vi1.x; w1.y = vj1.y - vi1.y;
        w1.z = vj1.z - vi1.z; w1.w = vj1.w - vi1.w;

        float dot0, dotd;
        dot0 = e0.x * u0.x;              dot0 = fmaf(e0.y, u0.y, dot0);
        dot0 = fmaf(e0.z, u0.z, dot0);   dot0 = fmaf(e0.w, u0.w, dot0);
        dot0 = fmaf(e1.x, u1.x, dot0);   dot0 = fmaf(e1.y, u1.y, dot0);
        dot0 = fmaf(e1.z, u1.z, dot0);   dot0 = fmaf(e1.w, u1.w, dot0);
        dotd = e0.x * w0.x;              dotd = fmaf(e0.y, w0.y, dotd);
        dotd = fmaf(e0.z, w0.z, dotd);   dotd = fmaf(e0.w, w0.w, dotd);
        dotd = fmaf(e1.x, w1.x, dotd);   dotd = fmaf(e1.y, w1.y, dotd);
        dotd = fmaf(e1.z, w1.z, dotd);   dotd = fmaf(e1.w, w1.w, dotd);

        dual_warp_sum(dot0, dotd, lane);

        float em = xm_i * xm_j;
        bool am = em > 0.f;

        float sc = am ? (dot0 + c_i) * em * 0.125f : -1e9f;
        float mn = fmaxf(m, sc);
        float alpha = __expf(m - mn);
        float pv = __expf(sc - mn);
        l = l * alpha + pv;
        float pve = pv * em;
        tacc = tacc * alpha + pve;
        s0.x = fmaf(s0.x, alpha, pve * e0.x);
        s0.y = fmaf(s0.y, alpha, pve * e0.y);
        s0.z = fmaf(s0.z, alpha, pve * e0.z);
        s0.w = fmaf(s0.w, alpha, pve * e0.w);
        s1.x = fmaf(s1.x, alpha, pve * e1.x);
        s1.y = fmaf(s1.y, alpha, pve * e1.y);
        s1.z = fmaf(s1.z, alpha, pve * e1.z);
        s1.w = fmaf(s1.w, alpha, pve * e1.w);
        m = mn;

        float o0 = 0.f, o1 = 0.f;
        if (am) {
            float arg = (dotd + dj - di) * em * 0.125f;
            float ai = 1.f / (1.f + __expf(-arg));
            float aj = 1.f - ai;
            o0 = (ai * vnj.x + aj * vni.x) * em;
            o1 = (ai * vnj.y + aj * vni.y) * em;
        }
        __stcg(reinterpret_cast<float2*>(out_e + ((size_t)r * Nn + j) * DHh + 2 * lane),
               make_float2(o0, o1));

        j = jn;
        e0 = ne0; e1 = ne1;
    }

    big[wid * Dd + d0 + 0] = s0.x; big[wid * Dd + d0 + 1] = s0.y;
    big[wid * Dd + d0 + 2] = s0.z; big[wid * Dd + d0 + 3] = s0.w;
    big[wid * Dd + d1 + 0] = s1.x; big[wid * Dd + d1 + 1] = s1.y;
    big[wid * Dd + d1 + 2] = s1.z; big[wid * Dd + d1 + 3] = s1.w;
    if (lane == 0) { mw[wid] = m; lw[wid] = l; tw[wid] = tacc; }
    __syncthreads();

    {
        float gm = mw[0];
        #pragma unroll
        for (int w = 1; w < 8; ++w) gm = fmaxf(gm, mw[w]);
        float gl = 0.f, gt = 0.f, gs = 0.f;
        #pragma unroll
        for (int w = 0; w < 8; ++w) {
            float sc2 = __expf(mw[w] - gm);
            gl = fmaf(lw[w], sc2, gl);
            gt = fmaf(tw[w], sc2, gt);
            gs = fmaf(big[w * Dd + t], sc2, gs);
        }
        float invl = 1.f / gl;
        gsrow[t] = gs * invl;
        if (t == 0) gt_s = gt * invl;
    }

    // ---- phase 2: n2n self attention for row r ----
    const float* Q = g_np + 3 * (size_t)BND;
    const float* K = g_np + 4 * (size_t)BND;
    const float* V = g_np + 5 * (size_t)BND;

    if (t < DHh) Q_s[t] = Q[(size_t)r * DHh + t];

    for (int tt = 0; tt < 2; ++tt) {
        __syncthreads();
        for (int idx = t; idx < 128 * 64; idx += 256) {
            int row = idx >> 6, col = idx & 63;
            big[row * 65 + col] = K[(size_t)(b * Nn + tt * 128 + row) * DHh + col];
        }
        __syncthreads();
        int row = t & 127, half = t >> 7;
        float p = 0.f;
        #pragma unroll 8
        for (int d = 0; d < 32; ++d)
            p = fmaf(Q_s[half * 32 + d], big[row * 65 + half * 32 + d], p);
        red[t] = p;
        __syncthreads();
        if (t < 128) att[tt * 128 + t] = red[t] + red[t + 128];
    }
    __syncthreads();

    {
        float xm_j = maskb_s[t];
        bool am = (xm_i * xm_j) > 0.f;
        float lg = am ? att[t] * 0.125f : -1e9f;
        float wmax = lg;
        #pragma unroll
        for (int o = 16; o; o >>= 1)
            wmax = fmaxf(wmax, __shfl_xor_sync(0xffffffffu, wmax, o));
        if (lane == 0) red[wid] = wmax;
        __syncthreads();
        float gmax = red[0];
        #pragma unroll
        for (int w = 1; w < 8; ++w) gmax = fmaxf(gmax, red[w]);
        float ex = __expf(lg - gmax);
        float wsum = ex;
        #pragma unroll
        for (int o = 16; o; o >>= 1)
            wsum += __shfl_xor_sync(0xffffffffu, wsum, o);
        if (lane == 0) red[8 + wid] = wsum;
        __syncthreads();
        float gsum = 0.f;
        #pragma unroll
        for (int w = 0; w < 8; ++w) gsum += red[8 + w];
        att[t] = ex / gsum;
    }
    __syncthreads();

    {
        int q = t >> 6, h = t & 63;
        float acc = 0.f;
        const float* Vb = V + (size_t)(b * Nn + q * 64) * DHh + h;
        #pragma unroll 8
        for (int jj = 0; jj < 64; ++jj)
            acc = fmaf(att[q * 64 + jj], Vb[(size_t)jj * DHh], acc);
        part[q][h] = acc;
    }
    __syncthreads();
    if (t < DHh)
        xsf_s[t] = (part[0][t] + part[1][t] + part[2][t] + part[3][t]) * xm_i;
    __syncthreads();

    {
        int q = t >> 6, h = t & 63;
        float acc = (q == 0) ? gt_s * bv[h] : 0.f;
        #pragma unroll 8
        for (int d = 0; d < 64; ++d)
            acc = fmaf(gsrow[q * 64 + d], Wv[(q * 64 + d) * DHh + h], acc);
        part[q][h] = acc;
    }
    __syncthreads();
    if (t < DHh) xc_s[t] = part[0][t] + part[1][t] + part[2][t] + part[3][t];
    __syncthreads();

    if (t < 128) {
        int half = t >> 6, hh = t & 63;
        float o = (half == 0) ? bmix[hh] : 0.f;
        #pragma unroll 8
        for (int k = 0; k < 64; ++k) {
            float src = (half == 0) ? xc_s[k] : xsf_s[k];
            o = fmaf(src, Wmix[(half * 64 + k) * DHh + hh], o);
        }
        part[half][hh] = o;
    }
    __syncthreads();
    if (t < DHh) out_x[(size_t)r * DHh + t] = part[0][t] + part[1][t];
}

extern "C" void kernel_launch(void* const* d_in, const int* in_sizes, int n_in,
                              void* d_out, int out_size)
{
    const float* x       = (const float*)d_in[0];
    const float* e       = (const float*)d_in[1];
    const float* mask    = (const float*)d_in[2];
    const float* W_n2e_q = (const float*)d_in[3];  const float* b_n2e_q = (const float*)d_in[4];
    const float* W_n2e_k = (const float*)d_in[5];  const float* b_n2e_k = (const float*)d_in[6];
    const float* W_n2e_v = (const float*)d_in[7];  const float* b_n2e_v = (const float*)d_in[8];
    const float* W_e2n_q = (const float*)d_in[9];  const float* b_e2n_q = (const float*)d_in[10];
    const float* W_e2n_k = (const float*)d_in[11]; const float* b_e2n_k = (const float*)d_in[12];
    const float* W_e2n_v = (const float*)d_in[13]; const float* b_e2n_v = (const float*)d_in[14];
    const float* W_n2n_q = (const float*)d_in[15]; const float* b_n2n_q = (const float*)d_in[16];
    const float* W_n2n_k = (const float*)d_in[17]; const float* b_n2n_k = (const float*)d_in[18];
    const float* W_n2n_v = (const float*)d_in[19]; const float* b_n2n_v = (const float*)d_in[20];
    const float* W_mix   = (const float*)d_in[21]; const float* b_mix   = (const float*)d_in[22];

    float* out   = (float*)d_out;
    float* out_x = out;
    float* out_e = out + (size_t)Bn * Nn * DHh;

    proj_x_kernel<<<dim3(64, 7), 256>>>(x, mask,
        W_n2e_q, b_n2e_q,   // slot0 = Qn
        W_e2n_k, b_e2n_k,   // slot1 = Kn
        W_e2n_v, b_e2n_v,   // slot2 = Vn
        W_n2n_q, b_n2n_q,   // slot3 = Q
        W_n2n_k, b_n2n_k,   // slot4 = K
        W_n2n_v, b_n2n_v,   // slot5 = V
        W_n2e_k, W_e2n_q);  // transposed by y==6 blocks

    make_uv_kernel<<<dim3(64, 4), 256>>>(b_n2e_k, b_e2n_q);

    fused_kernel<<<BNr, 256>>>(e, mask,
        W_n2e_v, b_n2e_v, W_mix, b_mix, out_e, out_x);
}